// round 13
// baseline (speedup 1.0000x reference)
#include <cuda_runtime.h>
#include <cuda_fp16.h>
#include <math.h>
#include <cstdint>

#define NB 8
#define NL 1024
#define NC 256
#define NH 8
#define HD 32
#define NT (NB*NL)   /* 8192 tokens */

// ------------------------- scratch (device globals) -------------------------
static __device__ __align__(16) __half g_x16[NT*NC];      // fp16 x, word-permuted ci
static __device__ __align__(16) __half g_y16[NT*NC];      // fp16 y, word-permuted ci
static __device__ __align__(16) __half g_wt16[3*9*NC*NC]; // conv w [conv][tap][co][ci-perm]
static __device__ __align__(16) __half g_cv16[3*NT*NC];   // conv out, word-permuted ch
static __device__ __align__(16) __half g_q16[NT*NC];      // Q [bh][L][32] dim-perm
static __device__ __align__(16) __half g_k16[NT*NC];      // K [bh][L][32] dim-perm
static __device__ __align__(16) __half g_v16t[NT*NC];     // V^T [bh][32][L] tok-perm
static __device__ __align__(16) __half g_ao16[NT*NC];     // attn out [t][256] ch-perm
static __device__ __align__(16) __half g_wf16[3*NC*NC];   // folded proj w, ci-perm
static __device__ __align__(16) __half g_wo16[NC*NC];     // Wo fp16, ci-perm
static __device__ float g_part[3*64*2*NC];
static __device__ float g_ab[3*2*NC];
static __device__ float g_bf[3*NC];

// ------------------------------ helpers -------------------------------------
__device__ __forceinline__ uint32_t cvta_s(const void* p) {
    return (uint32_t)__cvta_generic_to_shared(p);
}
__device__ __forceinline__ void cp16(uint32_t d, const void* s, uint32_t sz) {
    asm volatile("cp.async.cg.shared.global [%0], [%1], 16, %2;"
                 :: "r"(d), "l"(s), "r"(sz));
}
#define CP_COMMIT() asm volatile("cp.async.commit_group;")
#define CP_WAIT1()  asm volatile("cp.async.wait_group 1;")
#define CP_WAIT0()  asm volatile("cp.async.wait_group 0;")

__device__ __forceinline__ void mma_f16(float* c, const uint32_t* a, const uint32_t* b) {
    asm volatile(
        "mma.sync.aligned.m16n8k16.row.col.f32.f16.f16.f32 "
        "{%0,%1,%2,%3}, {%4,%5,%6,%7}, {%8,%9}, {%0,%1,%2,%3};"
        : "+f"(c[0]), "+f"(c[1]), "+f"(c[2]), "+f"(c[3])
        : "r"(a[0]), "r"(a[1]), "r"(a[2]), "r"(a[3]), "r"(b[0]), "r"(b[1]));
}

// word permutation within each 8-word (16-channel) group:
// storage word j holds orig word perm8(j); inv8 is its inverse.
__device__ __forceinline__ int perm8(int j) { return ((j & 1) << 2) | (j >> 1); }
__device__ __forceinline__ int inv8(int w)  { return ((w & 3) << 1) | (w >> 2); }
// storage channel index s -> original channel index
__device__ __forceinline__ int orig_ch(int s) {
    return (s & ~15) | (perm8((s & 15) >> 1) << 1) | (s & 1);
}
__device__ __forceinline__ __half2 f2h2(float a, float b) {
    return __floats2half2_rn(a, b);
}

// ---------------------------------------------------------------------------
// Implicit 3x3 conv on fp16 tensor cores (m16n8k16), halo smem reuse.
// Tile M=128 tokens x N=64 co; 8 warps (4m x 2n), warp 32x32.
// K-loop: 16 ci-chunks of 16. Output: fp16, channel-word-permuted.
// occ 4 (64-reg cap) for latency hiding.
// ---------------------------------------------------------------------------
#define CONV_A_H 3264   /* 204 cells * 16 halves */
#define CONV_B_H 9216   /* 576 rows * 16 halves */
#define CONV_NCH 16

__global__ __launch_bounds__(256, 4) void conv_gemm_kernel()
{
    extern __shared__ __half smh[];
    __half* sA[2] = { smh, smh + CONV_A_H };
    __half* sB[2] = { smh + 2*CONV_A_H, smh + 2*CONV_A_H + CONV_B_H };

    const int z = blockIdx.z;
    const __half* Ain = (z == 0) ? g_x16 : g_y16;
    const __half* Wtz = g_wt16 + (long)z * 9*NC*NC;
    __half* outh = g_cv16 + (long)z * NT*NC;

    const int tid = threadIdx.x;
    const int wid = tid >> 5, lane = tid & 31;
    const int gID = lane >> 2, tq = lane & 3;
    const int wm = (wid >> 1) * 32, wn = (wid & 1) * 32;
    const int m0 = blockIdx.x * 128, n0 = blockIdx.y * 64;
    const int bImg = blockIdx.x >> 3;
    const int r0b  = (blockIdx.x & 7) * 4;

    auto load_stage = [&](int cc, int st) {
        const int ci0 = cc * 16;
        for (int q = tid; q < 408; q += 256) {
            const int cell = q >> 1, h8 = q & 1;
            const int hr = cell / 34, hc = cell - hr*34;
            const int ir = r0b + hr - 1, ic = hc - 1;
            const bool ok = ((unsigned)ir < 32u) && ((unsigned)ic < 32u);
            const __half* src = ok ? &Ain[((bImg<<10) + ir*32 + ic)*NC + ci0 + h8*8]
                                   : Ain;
            cp16(cvta_s(&sA[st][cell*16 + h8*8]), src, ok ? 16 : 0);
        }
        for (int q = tid; q < 1152; q += 256) {
            const int rowc = q >> 1, h8 = q & 1;
            const int tap = rowc >> 6, co = rowc & 63;
            const __half* src = &Wtz[((tap<<8) + n0 + co)*NC + ci0 + h8*8];
            cp16(cvta_s(&sB[st][rowc*16 + h8*8]), src, 16);
        }
    };

    float acc[2][4][4];
    #pragma unroll
    for (int i = 0; i < 2; i++)
        #pragma unroll
        for (int j = 0; j < 4; j++)
            #pragma unroll
            for (int c = 0; c < 4; c++) acc[i][j][c] = 0.f;

    load_stage(0, 0); CP_COMMIT();

    for (int cc = 0; cc < CONV_NCH; cc++) {
        const int cur = cc & 1;
        if (cc + 1 < CONV_NCH) { load_stage(cc + 1, cur ^ 1); CP_COMMIT(); CP_WAIT1(); }
        else                   { CP_WAIT0(); }
        __syncthreads();
        const __half* a = sA[cur];
        const __half* b = sB[cur];

        #pragma unroll
        for (int tap = 0; tap < 9; tap++) {
            const int d3 = tap / 3, m3 = tap - d3*3;
            uint32_t bf2[4][2];
            #pragma unroll
            for (int nt = 0; nt < 4; nt++) {
                const uint2 bv = *(const uint2*)&b[(tap*64 + wn + nt*8 + gID)*16 + tq*4];
                bf2[nt][0] = bv.x; bf2[nt][1] = bv.y;
            }
            #pragma unroll
            for (int mt = 0; mt < 2; mt++) {
                const int base = wm + mt*16;
                const int rA = base >> 5, cA0 = base & 31;
                const int cell = (rA + d3)*34 + cA0 + gID + m3;
                const uint2 a02 = *(const uint2*)&a[cell*16 + tq*4];
                const uint2 a13 = *(const uint2*)&a[(cell + 8)*16 + tq*4];
                uint32_t af[4] = { a02.x, a13.x, a02.y, a13.y };
                #pragma unroll
                for (int nt = 0; nt < 4; nt++)
                    mma_f16(acc[mt][nt], af, bf2[nt]);
            }
        }
        __syncthreads();
    }

    #pragma unroll
    for (int mt = 0; mt < 2; mt++) {
        #pragma unroll
        for (int half = 0; half < 2; half++) {
            const int t = m0 + wm + mt*16 + gID + half*8;
            #pragma unroll
            for (int nt = 0; nt < 4; nt++) {
                const int n = n0 + wn + nt*8 + tq*2;
                const int g = n >> 4, wd = (n & 15) >> 1;
                const int off = t*NC + (g << 4) + (inv8(wd) << 1);
                *(__half2*)&outh[off] = f2h2(acc[mt][nt][half*2 + 0],
                                             acc[mt][nt][half*2 + 1]);
            }
        }
    }
}

// ---------------------------------------------------------------------------
// Unified fp16 tensor-core GEMM: out[t,n] = sum_k A[t,k]*B[n,k] (+bias).
// A, B fp16 with word-permuted k. Tile M=128 x N=64, 8 warps, K-chunks of 32.
// Rows padded to 48 halves (bank-conflict-free LDS.64 fragments). occ 3.
// split=0: fp32 natural out. split=1: per-z fp16 Q/K (dim-perm) or V^T (tok-perm).
// ---------------------------------------------------------------------------
__global__ __launch_bounds__(256, 3) void gemm16_kernel(
    const __half* __restrict__ A0, const __half* __restrict__ A1,
    const __half* __restrict__ A2,
    const __half* __restrict__ B0, long bStride,
    const float* __restrict__ bias0, float* __restrict__ outF, int split)
{
    extern __shared__ __half smh[];
    __half* sA[2] = { smh, smh + 6144 };
    __half* sB[2] = { smh + 12288, smh + 12288 + 3072 };

    const int z = blockIdx.z;
    const __half* A  = (z == 0) ? A0 : ((z == 1) ? A1 : A2);
    const __half* Bw = B0 + (long)z * bStride;
    const float* bias = bias0 ? (bias0 + z*NC) : nullptr;

    const int tid = threadIdx.x;
    const int wid = tid >> 5, lane = tid & 31;
    const int gID = lane >> 2, tq = lane & 3;
    const int wm = (wid >> 1) * 32, wn = (wid & 1) * 32;
    const int m0 = blockIdx.x * 128, n0 = blockIdx.y * 64;

    auto load_stage = [&](int ch, int st) {
        const int k0 = ch * 32;
        #pragma unroll
        for (int u = 0; u < 2; u++) {
            const int q = u*256 + tid, row = q >> 2, gr = q & 3;
            cp16(cvta_s(&sA[st][row*48 + gr*8]), &A[(m0+row)*NC + k0 + gr*8], 16);
        }
        {
            const int row = tid >> 2, gr = tid & 3;
            cp16(cvta_s(&sB[st][row*48 + gr*8]), &Bw[(n0+row)*NC + k0 + gr*8], 16);
        }
    };

    float acc[2][4][4];
    #pragma unroll
    for (int i = 0; i < 2; i++)
        #pragma unroll
        for (int j = 0; j < 4; j++)
            #pragma unroll
            for (int c = 0; c < 4; c++) acc[i][j][c] = 0.f;

    load_stage(0, 0); CP_COMMIT();

    for (int ch = 0; ch < 8; ch++) {
        const int cur = ch & 1;
        if (ch + 1 < 8) { load_stage(ch + 1, cur ^ 1); CP_COMMIT(); CP_WAIT1(); }
        else            { CP_WAIT0(); }
        __syncthreads();
        const __half* a = sA[cur];
        const __half* b = sB[cur];

        #pragma unroll
        for (int g2 = 0; g2 < 2; g2++) {
            uint32_t bf2[4][2];
            #pragma unroll
            for (int nt = 0; nt < 4; nt++) {
                const uint2 bv = *(const uint2*)&b[(wn + nt*8 + gID)*48 + g2*16 + tq*4];
                bf2[nt][0] = bv.x; bf2[nt][1] = bv.y;
            }
            #pragma unroll
            for (int mt = 0; mt < 2; mt++) {
                const __half* pa = &a[(wm + mt*16 + gID)*48 + g2*16 + tq*4];
                const uint2 a02 = *(const uint2*)pa;
                const uint2 a13 = *(const uint2*)&pa[8*48];
                uint32_t af[4] = { a02.x, a13.x, a02.y, a13.y };
                #pragma unroll
                for (int nt = 0; nt < 4; nt++)
                    mma_f16(acc[mt][nt], af, bf2[nt]);
            }
        }
        __syncthreads();
    }

    #pragma unroll
    for (int mt = 0; mt < 2; mt++) {
        #pragma unroll
        for (int half = 0; half < 2; half++) {
            const int t = m0 + wm + mt*16 + gID + half*8;
            #pragma unroll
            for (int nt = 0; nt < 4; nt++) {
                const int n = n0 + wn + nt*8 + tq*2;
                float v0 = acc[mt][nt][half*2 + 0];
                float v1 = acc[mt][nt][half*2 + 1];
                if (bias) { v0 += bias[n]; v1 += bias[n+1]; }
                if (!split) {
                    float2 v = { v0, v1 };
                    *(float2*)&outF[t*NC + n] = v;
                } else {
                    const int bb = t >> 10, tt = t & 1023;
                    const int h = n >> 5, d = n & 31;
                    if (z < 2) {
                        __half* dst = (z == 0) ? g_q16 : g_k16;
                        const int g = d >> 4, wd = (d & 15) >> 1;
                        const int off = ((bb*NH + h)*NL + tt)*HD + (g << 4) + (inv8(wd) << 1);
                        *(__half2*)&dst[off] = f2h2(v0, v1);
                    } else {
                        const int wt = (tt & 15) >> 1;
                        const int tp = (tt & ~15) | (inv8(wt) << 1) | (tt & 1);
                        const long base = (long)(bb*NH + h) * HD;
                        g_v16t[(base + d    )*NL + tp] = __float2half_rn(v0);
                        g_v16t[(base + d + 1)*NL + tp] = __float2half_rn(v1);
                    }
                }
            }
        }
    }
}

// ---------------------------------------------------------------------------
// fp16 tensor-core flash attention; fp32 softmax. occ 6.
// Block = 128 threads (4 warps x 16 q rows). grid (64 bh, 16 q-tiles).
// K: [64 tok][32 dim-perm] stride 48; V^T: [32 dim][64 tok-perm] stride 80;
// P: [64 q][64 tok-perm half] stride 80. All fragments LDS.64, conflict-free.
// ---------------------------------------------------------------------------
#define ARS 48
#define AVS 80
#define APS 80

__global__ __launch_bounds__(128, 6) void attn16_kernel()
{
    extern __shared__ __half smh[];
    __half* sK[2]  = { smh, smh + 64*ARS };
    __half* sVt[2] = { smh + 2*64*ARS, smh + 2*64*ARS + 32*AVS };
    __half* sP     = smh + 2*64*ARS + 2*32*AVS;

    const int bh = blockIdx.x, qt = blockIdx.y;
    const int tid = threadIdx.x, w = tid >> 5, lane = tid & 31;
    const int gID = lane >> 2, tq = lane & 3;
    const int r0 = qt*64 + w*16;
    const __half* Qb = g_q16 + (long)bh*NL*HD;
    const __half* Kb = g_k16 + (long)bh*NL*HD;
    const __half* Vb = g_v16t + (long)bh*HD*NL;   // [32][1024]

    const __half2 sc2 = __floats2half2_rn(0.0625f, 0.0625f);
    uint32_t qf[2][4];
    #pragma unroll
    for (int g = 0; g < 2; g++) {
        uint2 lo = *(const uint2*)&Qb[(r0+gID  )*HD + g*16 + tq*4];
        uint2 hi = *(const uint2*)&Qb[(r0+gID+8)*HD + g*16 + tq*4];
        __half2 t;
        t = __hmul2(*(__half2*)&lo.x, sc2); qf[g][0] = *(uint32_t*)&t;
        t = __hmul2(*(__half2*)&hi.x, sc2); qf[g][1] = *(uint32_t*)&t;
        t = __hmul2(*(__half2*)&lo.y, sc2); qf[g][2] = *(uint32_t*)&t;
        t = __hmul2(*(__half2*)&hi.y, sc2); qf[g][3] = *(uint32_t*)&t;
    }

    float m0 = -1e30f, m1 = -1e30f, l0 = 0.f, l1 = 0.f;
    float oacc[4][4];
    #pragma unroll
    for (int i = 0; i < 4; i++)
        #pragma unroll
        for (int j = 0; j < 4; j++) oacc[i][j] = 0.f;

    auto load_kv = [&](int kt, int st) {
        #pragma unroll
        for (int u = 0; u < 2; u++) {
            const int q = u*128 + tid, row = q >> 2, gr = q & 3;
            cp16(cvta_s(&sK[st][row*ARS + gr*8]), &Kb[(kt*64 + row)*HD + gr*8], 16);
        }
        #pragma unroll
        for (int u = 0; u < 2; u++) {
            const int q = u*128 + tid, row = q >> 3, gr = q & 7;
            cp16(cvta_s(&sVt[st][row*AVS + gr*8]), &Vb[row*NL + kt*64 + gr*8], 16);
        }
    };

    load_kv(0, 0); CP_COMMIT();

    for (int kt = 0; kt < 16; kt++) {
        const int cur = kt & 1;
        if (kt + 1 < 16) { load_kv(kt + 1, cur ^ 1); CP_COMMIT(); CP_WAIT1(); }
        else             { CP_WAIT0(); }
        __syncthreads();

        // S = Q K^T (16 x 64 per warp): 16 MMAs
        float sacc[8][4];
        #pragma unroll
        for (int nt = 0; nt < 8; nt++)
            #pragma unroll
            for (int c = 0; c < 4; c++) sacc[nt][c] = 0.f;
        #pragma unroll
        for (int g = 0; g < 2; g++) {
            #pragma unroll
            for (int nt = 0; nt < 8; nt++) {
                const uint2 bv = *(const uint2*)&sK[cur][(nt*8 + gID)*ARS + g*16 + tq*4];
                uint32_t bf[2] = { bv.x, bv.y };
                mma_f16(sacc[nt], qf[g], bf);
            }
        }

        // online softmax
        float mx0 = -1e30f, mx1 = -1e30f;
        #pragma unroll
        for (int nt = 0; nt < 8; nt++) {
            mx0 = fmaxf(mx0, fmaxf(sacc[nt][0], sacc[nt][1]));
            mx1 = fmaxf(mx1, fmaxf(sacc[nt][2], sacc[nt][3]));
        }
        mx0 = fmaxf(mx0, __shfl_xor_sync(~0u, mx0, 1));
        mx0 = fmaxf(mx0, __shfl_xor_sync(~0u, mx0, 2));
        mx1 = fmaxf(mx1, __shfl_xor_sync(~0u, mx1, 1));
        mx1 = fmaxf(mx1, __shfl_xor_sync(~0u, mx1, 2));
        const float mn0 = fmaxf(m0, mx0), mn1 = fmaxf(m1, mx1);
        const float c0 = __expf(m0 - mn0), c1 = __expf(m1 - mn1);

        float s0 = 0.f, s1 = 0.f;
        #pragma unroll
        for (int nt = 0; nt < 8; nt++) {
            float p0 = __expf(sacc[nt][0] - mn0);
            float p1 = __expf(sacc[nt][1] - mn0);
            float p2 = __expf(sacc[nt][2] - mn1);
            float p3 = __expf(sacc[nt][3] - mn1);
            s0 += p0 + p1; s1 += p2 + p3;
            const int colw = nt*8 + tq*2;
            const int po = ((colw >> 4) << 4) + inv8((colw & 15) >> 1)*2;
            *(__half2*)&sP[(w*16 + gID    )*APS + po] = f2h2(p0, p1);
            *(__half2*)&sP[(w*16 + gID + 8)*APS + po] = f2h2(p2, p3);
        }
        s0 += __shfl_xor_sync(~0u, s0, 1); s0 += __shfl_xor_sync(~0u, s0, 2);
        s1 += __shfl_xor_sync(~0u, s1, 1); s1 += __shfl_xor_sync(~0u, s1, 2);
        l0 = l0*c0 + s0; l1 = l1*c1 + s1;
        #pragma unroll
        for (int nt = 0; nt < 4; nt++) {
            oacc[nt][0] *= c0; oacc[nt][1] *= c0;
            oacc[nt][2] *= c1; oacc[nt][3] *= c1;
        }
        m0 = mn0; m1 = mn1;
        __syncwarp();

        // O += P V : 16 MMAs
        #pragma unroll
        for (int ks = 0; ks < 4; ks++) {
            const __half* prow = &sP[(w*16 + gID)*APS + ks*16 + tq*4];
            const uint2 a02 = *(const uint2*)prow;
            const uint2 a13 = *(const uint2*)&prow[8*APS];
            uint32_t pa[4] = { a02.x, a13.x, a02.y, a13.y };
            #pragma unroll
            for (int nt = 0; nt < 4; nt++) {
                const uint2 bv = *(const uint2*)&sVt[cur][(nt*8 + gID)*AVS + ks*16 + tq*4];
                uint32_t vb[2] = { bv.x, bv.y };
                mma_f16(oacc[nt], pa, vb);
            }
        }
        __syncthreads();
    }

    const float i0 = 1.f / l0, i1 = 1.f / l1;
    const int b = bh >> 3, h = bh & 7;
    #pragma unroll
    for (int nt = 0; nt < 4; nt++) {
        const int ch = h*HD + nt*8 + tq*2;
        const int off = ((ch >> 4) << 4) + inv8((ch & 15) >> 1)*2;
        *(__half2*)&g_ao16[(b*NL + r0 + gID    )*NC + off] =
            f2h2(oacc[nt][0]*i0, oacc[nt][1]*i0);
        *(__half2*)&g_ao16[(b*NL + r0 + gID + 8)*NC + off] =
            f2h2(oacc[nt][2]*i1, oacc[nt][3]*i1);
    }
}

// ------------------------ small prep / stats kernels ------------------------
__global__ __launch_bounds__(256) void cvt_xy_kernel(
    const float* __restrict__ x, const float* __restrict__ y)
{
    const float* s = blockIdx.y ? y : x;
    __half* d = blockIdx.y ? g_y16 : g_x16;
    const int base = (blockIdx.x * 256 + threadIdx.x) * 8;
    const int token = base >> 8;
    const int cs0 = base & 255;
    __half tmp[8];
    #pragma unroll
    for (int jj = 0; jj < 8; jj++)
        tmp[jj] = __float2half_rn(s[token*NC + orig_ch(cs0 + jj)]);
    *(uint4*)&d[base] = *(const uint4*)tmp;
}

__global__ __launch_bounds__(256) void round_wo_kernel(const float* __restrict__ Wo)
{
    const int idx = blockIdx.x * 256 + threadIdx.x;   // co*256 + storage ci
    const int ci = idx & 255, co = idx >> 8;
    g_wo16[idx] = __float2half_rn(Wo[co*NC + orig_ch(ci)]);
}

__global__ __launch_bounds__(256) void wtrans_kernel(
    const float* __restrict__ wq, const float* __restrict__ wk,
    const float* __restrict__ wv)
{
    const float* W = (blockIdx.y == 0) ? wq : (blockIdx.y == 1) ? wk : wv;
    __half* dst = g_wt16 + (long)blockIdx.y * 9*NC*NC;
    const int idx = blockIdx.x * 256 + threadIdx.x;
    const int ci  = idx & 255;
    const int rem = idx >> 8;
    const int co  = rem & 255;
    const int tap = rem >> 8;
    dst[idx] = __float2half_rn(W[(co*NC + orig_ch(ci))*9 + tap]);
}

__global__ __launch_bounds__(256) void stats_partial_kernel()
{
    const __half* src = g_cv16 + (long)blockIdx.y * NT*NC;
    const int c = threadIdx.x;
    float s = 0.f, s2 = 0.f;
    const int t0 = blockIdx.x * (NT/64);
    #pragma unroll 4
    for (int t = t0; t < t0 + NT/64; t++) {
        float val = __half2float(src[t*NC + c]);
        s += val; s2 += val*val;
    }
    g_part[((blockIdx.y*64 + blockIdx.x)*2 + 0)*NC + c] = s;
    g_part[((blockIdx.y*64 + blockIdx.x)*2 + 1)*NC + c] = s2;
}

__global__ __launch_bounds__(1024) void stats_final_kernel(
    const float* __restrict__ gq, const float* __restrict__ bq,
    const float* __restrict__ gk, const float* __restrict__ bk,
    const float* __restrict__ gv, const float* __restrict__ bv)
{
    const int s = blockIdx.x;
    const int c = threadIdx.x & 255;        // storage channel
    const int seg = threadIdx.x >> 8;
    float sum = 0.f, sum2 = 0.f;
    #pragma unroll
    for (int i = seg*16; i < seg*16 + 16; i++) {
        sum  += g_part[((s*64+i)*2 + 0)*NC + c];
        sum2 += g_part[((s*64+i)*2 + 1)*NC + c];
    }
    __shared__ float red[8][256];
    red[seg][c] = sum; red[4+seg][c] = sum2;
    __syncthreads();
    if (seg == 0) {
        sum  = red[0][c] + red[1][c] + red[2][c] + red[3][c];
        sum2 = red[4][c] + red[5][c] + red[6][c] + red[7][c];
        float mu  = sum  * (1.f/NT);
        float var = sum2 * (1.f/NT) - mu*mu;
        const float* gam = (s == 0) ? gq : (s == 1) ? gk : gv;
        const float* bet = (s == 0) ? bq : (s == 1) ? bk : bv;
        const int oc = orig_ch(c);
        float a  = gam[oc] * rsqrtf(var + 1e-5f);
        float bb = bet[oc] - mu*a;
        g_ab[(s*2+0)*NC + c] = a;
        g_ab[(s*2+1)*NC + c] = bb;
    }
}

__global__ __launch_bounds__(256) void fold_kernel(
    const float* __restrict__ Wq, const float* __restrict__ Wk,
    const float* __restrict__ Wv)
{
    const int s  = blockIdx.y;
    const int co = blockIdx.x;
    const int c  = threadIdx.x;            // storage channel
    const float* W = (s == 0) ? Wq : (s == 1) ? Wk : Wv;
    float a  = g_ab[(s*2+0)*NC + c];
    float bb = g_ab[(s*2+1)*NC + c];
    float wv = W[co*NC + orig_ch(c)];
    g_wf16[s*NC*NC + co*NC + c] = __float2half_rn(wv * a);

    __shared__ float red[256];
    red[c] = wv * bb;
    __syncthreads();
    for (int o = 128; o > 0; o >>= 1) {
        if (c < o) red[c] += red[c + o];
        __syncthreads();
    }
    if (c == 0) g_bf[s*NC + co] = red[0];
}

// ---------------------------------------------------------------------------

extern "C" void kernel_launch(void* const* d_in, const int* in_sizes, int n_in,
                              void* d_out, int out_size)
{
    const float* x        = (const float*)d_in[0];
    const float* y        = (const float*)d_in[1];
    const float* conv_q_w = (const float*)d_in[4];
    const float* bn_q_g   = (const float*)d_in[5];
    const float* bn_q_b   = (const float*)d_in[6];
    const float* conv_k_w = (const float*)d_in[7];
    const float* bn_k_g   = (const float*)d_in[8];
    const float* bn_k_b   = (const float*)d_in[9];
    const float* conv_v_w = (const float*)d_in[10];
    const float* bn_v_g   = (const float*)d_in[11];
    const float* bn_v_b   = (const float*)d_in[12];
    const float* Wq       = (const float*)d_in[13];
    const float* Wk       = (const float*)d_in[14];
    const float* Wv       = (const float*)d_in[15];
    const float* Wo       = (const float*)d_in[16];
    const float* bo       = (const float*)d_in[17];
    float* out = (float*)d_out;

    __half *cv16, *wf16, *ao16, *wo16;
    float *bf;
    cudaGetSymbolAddress((void**)&cv16, g_cv16);
    cudaGetSymbolAddress((void**)&wf16, g_wf16);
    cudaGetSymbolAddress((void**)&ao16, g_ao16);
    cudaGetSymbolAddress((void**)&wo16, g_wo16);
    cudaGetSymbolAddress((void**)&bf, g_bf);

    const int CONV_SMEM  = (CONV_A_H + CONV_B_H) * 2 * 2;         // 49920 B
    const int GEMM_SMEM  = (6144 + 3072) * 2 * 2;                 // 36864 B
    const int ATTN_SMEM  = (2*64*ARS + 2*32*AVS + 64*APS) * 2;    // 32768 B
    cudaFuncSetAttribute(conv_gemm_kernel,
                         cudaFuncAttributeMaxDynamicSharedMemorySize, CONV_SMEM);
    cudaFuncSetAttribute(gemm16_kernel,
                         cudaFuncAttributeMaxDynamicSharedMemorySize, GEMM_SMEM);
    cudaFuncSetAttribute(attn16_kernel,
                         cudaFuncAttributeMaxDynamicSharedMemorySize, ATTN_SMEM);

    // operand conversion + permuted weight layouts
    cvt_xy_kernel<<<dim3(NT*NC/2048, 2), 256>>>(x, y);
    wtrans_kernel<<<dim3(9*NC, 3), 256>>>(conv_q_w, conv_k_w, conv_v_w);
    round_wo_kernel<<<NC*NC/256, 256>>>(Wo);

    // 3 convs, halo implicit GEMM on fp16 tensor cores -> fp16 permuted output
    conv_gemm_kernel<<<dim3(NT/128, NC/64, 3), 256, CONV_SMEM>>>();

    // BN stats -> fold into fp16 projection weights
    stats_partial_kernel<<<dim3(64, 3), 256>>>();
    stats_final_kernel<<<3, 1024>>>(bn_q_g, bn_q_b, bn_k_g, bn_k_b, bn_v_g, bn_v_b);
    fold_kernel<<<dim3(NC, 3), 256>>>(Wq, Wk, Wv);

    // 3 projections (fp16): Q/K dim-permuted, V transposed token-permuted
    gemm16_kernel<<<dim3(NT/128, NC/64, 3), 256, GEMM_SMEM>>>(
        cv16, cv16 + (long)NT*NC, cv16 + (long)2*NT*NC,
        wf16, (long)NC*NC, bf, nullptr, 1);

    // fp16 flash attention
    attn16_kernel<<<dim3(NB*NH, NL/64), 128, ATTN_SMEM>>>();

    // output projection (fp16 GEMM, fp32 natural output)
    gemm16_kernel<<<dim3(NT/128, NC/64, 1), 256, GEMM_SMEM>>>(
        ao16, ao16, ao16, wo16, 0, bo, out, 0);
}

// round 14
// speedup vs baseline: 1.4028x; 1.4028x over previous
#include <cuda_runtime.h>
#include <cuda_fp16.h>
#include <math.h>
#include <cstdint>

#define NB 8
#define NL 1024
#define NC 256
#define NH 8
#define HD 32
#define NT (NB*NL)   /* 8192 tokens */

// ------------------------- scratch (device globals) -------------------------
static __device__ __align__(16) __half g_x16[NT*NC];      // fp16 x, word-permuted ci
static __device__ __align__(16) __half g_y16[NT*NC];      // fp16 y, word-permuted ci
static __device__ __align__(16) __half g_wt16[3*9*NC*NC]; // conv w [conv][tap][co][ci-perm]
static __device__ __align__(16) __half g_cv16[3*NT*NC];   // conv out, word-permuted ch
static __device__ __align__(16) __half g_q16[NT*NC];      // Q [bh][L][32] dim-perm
static __device__ __align__(16) __half g_k16[NT*NC];      // K [bh][L][32] dim-perm
static __device__ __align__(16) __half g_v16t[NT*NC];     // V^T [bh][32][L] tok-perm
static __device__ __align__(16) __half g_ao16[NT*NC];     // attn out [t][256] ch-perm
static __device__ __align__(16) __half g_wf16[3*NC*NC];   // folded proj w, ci-perm
static __device__ __align__(16) __half g_wo16[NC*NC];     // Wo fp16, ci-perm
static __device__ float g_part[3*64*2*NC];
static __device__ float g_ab[3*2*NC];
static __device__ float g_bf[3*NC];

// ------------------------------ helpers -------------------------------------
__device__ __forceinline__ uint32_t cvta_s(const void* p) {
    return (uint32_t)__cvta_generic_to_shared(p);
}
__device__ __forceinline__ void cp16(uint32_t d, const void* s, uint32_t sz) {
    asm volatile("cp.async.cg.shared.global [%0], [%1], 16, %2;"
                 :: "r"(d), "l"(s), "r"(sz));
}
#define CP_COMMIT() asm volatile("cp.async.commit_group;")
#define CP_WAIT1()  asm volatile("cp.async.wait_group 1;")
#define CP_WAIT0()  asm volatile("cp.async.wait_group 0;")

__device__ __forceinline__ void mma_f16(float* c, const uint32_t* a, const uint32_t* b) {
    asm volatile(
        "mma.sync.aligned.m16n8k16.row.col.f32.f16.f16.f32 "
        "{%0,%1,%2,%3}, {%4,%5,%6,%7}, {%8,%9}, {%0,%1,%2,%3};"
        : "+f"(c[0]), "+f"(c[1]), "+f"(c[2]), "+f"(c[3])
        : "r"(a[0]), "r"(a[1]), "r"(a[2]), "r"(a[3]), "r"(b[0]), "r"(b[1]));
}

// word permutation within each 8-word (16-channel) group:
// storage word j holds orig word perm8(j); inv8 is its inverse.
__device__ __forceinline__ int perm8(int j) { return ((j & 1) << 2) | (j >> 1); }
__device__ __forceinline__ int inv8(int w)  { return ((w & 3) << 1) | (w >> 2); }
// storage channel index s -> original channel index
__device__ __forceinline__ int orig_ch(int s) {
    return (s & ~15) | (perm8((s & 15) >> 1) << 1) | (s & 1);
}
__device__ __forceinline__ __half2 f2h2(float a, float b) {
    return __floats2half2_rn(a, b);
}

// ---------------------------------------------------------------------------
// Implicit 3x3 conv on fp16 tensor cores (m16n8k16), halo smem reuse.
// Tile M=128 tokens x N=64 co; 8 warps (4m x 2n), warp 32x32.
// K-loop: 16 ci-chunks of 16, unrolled x2 so buffer bases are compile-time
// (fragment addresses fold into LDS immediates). Output fp16, ch-word-permuted.
// ---------------------------------------------------------------------------
#define CONV_A_H 3264   /* 204 cells * 16 halves */
#define CONV_B_H 9216   /* 576 rows * 16 halves */
#define CONV_NCH 16

__global__ __launch_bounds__(256, 3) void conv_gemm_kernel()
{
    extern __shared__ __half smh[];
    __half* sA[2] = { smh, smh + CONV_A_H };
    __half* sB[2] = { smh + 2*CONV_A_H, smh + 2*CONV_A_H + CONV_B_H };

    const int z = blockIdx.z;
    const __half* Ain = (z == 0) ? g_x16 : g_y16;
    const __half* Wtz = g_wt16 + (long)z * 9*NC*NC;
    __half* outh = g_cv16 + (long)z * NT*NC;

    const int tid = threadIdx.x;
    const int wid = tid >> 5, lane = tid & 31;
    const int gID = lane >> 2, tq = lane & 3;
    const int wm = (wid >> 1) * 32, wn = (wid & 1) * 32;
    const int m0 = blockIdx.x * 128, n0 = blockIdx.y * 64;
    const int bImg = blockIdx.x >> 3;
    const int r0b  = (blockIdx.x & 7) * 4;

    auto load_stage = [&](int cc, int st) {
        const int ci0 = cc * 16;
        for (int q = tid; q < 408; q += 256) {
            const int cell = q >> 1, h8 = q & 1;
            const int hr = cell / 34, hc = cell - hr*34;
            const int ir = r0b + hr - 1, ic = hc - 1;
            const bool ok = ((unsigned)ir < 32u) && ((unsigned)ic < 32u);
            const __half* src = ok ? &Ain[((bImg<<10) + ir*32 + ic)*NC + ci0 + h8*8]
                                   : Ain;
            cp16(cvta_s(&sA[st][cell*16 + h8*8]), src, ok ? 16 : 0);
        }
        for (int q = tid; q < 1152; q += 256) {
            const int rowc = q >> 1, h8 = q & 1;
            const int tap = rowc >> 6, co = rowc & 63;
            const __half* src = &Wtz[((tap<<8) + n0 + co)*NC + ci0 + h8*8];
            cp16(cvta_s(&sB[st][rowc*16 + h8*8]), src, 16);
        }
    };

    float acc[2][4][4];
    #pragma unroll
    for (int i = 0; i < 2; i++)
        #pragma unroll
        for (int j = 0; j < 4; j++)
            #pragma unroll
            for (int c = 0; c < 4; c++) acc[i][j][c] = 0.f;

    load_stage(0, 0); CP_COMMIT();

    #pragma unroll 2
    for (int cc = 0; cc < CONV_NCH; cc++) {
        const int cur = cc & 1;
        if (cc + 1 < CONV_NCH) { load_stage(cc + 1, cur ^ 1); CP_COMMIT(); CP_WAIT1(); }
        else                   { CP_WAIT0(); }
        __syncthreads();
        const __half* a = sA[cur];
        const __half* b = sB[cur];

        #pragma unroll
        for (int tap = 0; tap < 9; tap++) {
            const int d3 = tap / 3, m3 = tap - d3*3;
            uint32_t bf2[4][2];
            #pragma unroll
            for (int nt = 0; nt < 4; nt++) {
                const uint2 bv = *(const uint2*)&b[(tap*64 + wn + nt*8 + gID)*16 + tq*4];
                bf2[nt][0] = bv.x; bf2[nt][1] = bv.y;
            }
            #pragma unroll
            for (int mt = 0; mt < 2; mt++) {
                const int base = wm + mt*16;
                const int rA = base >> 5, cA0 = base & 31;
                const int cell = (rA + d3)*34 + cA0 + gID + m3;
                const uint2 a02 = *(const uint2*)&a[cell*16 + tq*4];
                const uint2 a13 = *(const uint2*)&a[(cell + 8)*16 + tq*4];
                uint32_t af[4] = { a02.x, a13.x, a02.y, a13.y };
                #pragma unroll
                for (int nt = 0; nt < 4; nt++)
                    mma_f16(acc[mt][nt], af, bf2[nt]);
            }
        }
        __syncthreads();
    }

    #pragma unroll
    for (int mt = 0; mt < 2; mt++) {
        #pragma unroll
        for (int half = 0; half < 2; half++) {
            const int t = m0 + wm + mt*16 + gID + half*8;
            #pragma unroll
            for (int nt = 0; nt < 4; nt++) {
                const int n = n0 + wn + nt*8 + tq*2;
                const int g = n >> 4, wd = (n & 15) >> 1;
                const int off = t*NC + (g << 4) + (inv8(wd) << 1);
                *(__half2*)&outh[off] = f2h2(acc[mt][nt][half*2 + 0],
                                             acc[mt][nt][half*2 + 1]);
            }
        }
    }
}

// ---------------------------------------------------------------------------
// Unified fp16 tensor-core GEMM: out[t,n] = sum_k A[t,k]*B[n,k] (+bias).
// A, B fp16 with word-permuted k. Tile M=128 x N=64, 8 warps, K-chunks of 32,
// unrolled x2 for static buffer bases. Rows padded to 48 halves.
// split=0: fp32 natural out. split=1: per-z fp16 Q/K (dim-perm) or V^T (tok-perm).
// ---------------------------------------------------------------------------
__global__ __launch_bounds__(256) void gemm16_kernel(
    const __half* __restrict__ A0, const __half* __restrict__ A1,
    const __half* __restrict__ A2,
    const __half* __restrict__ B0, long bStride,
    const float* __restrict__ bias0, float* __restrict__ outF, int split)
{
    extern __shared__ __half smh[];
    __half* sA[2] = { smh, smh + 6144 };
    __half* sB[2] = { smh + 12288, smh + 12288 + 3072 };

    const int z = blockIdx.z;
    const __half* A  = (z == 0) ? A0 : ((z == 1) ? A1 : A2);
    const __half* Bw = B0 + (long)z * bStride;
    const float* bias = bias0 ? (bias0 + z*NC) : nullptr;

    const int tid = threadIdx.x;
    const int wid = tid >> 5, lane = tid & 31;
    const int gID = lane >> 2, tq = lane & 3;
    const int wm = (wid >> 1) * 32, wn = (wid & 1) * 32;
    const int m0 = blockIdx.x * 128, n0 = blockIdx.y * 64;

    auto load_stage = [&](int ch, int st) {
        const int k0 = ch * 32;
        #pragma unroll
        for (int u = 0; u < 2; u++) {
            const int q = u*256 + tid, row = q >> 2, gr = q & 3;
            cp16(cvta_s(&sA[st][row*48 + gr*8]), &A[(m0+row)*NC + k0 + gr*8], 16);
        }
        {
            const int row = tid >> 2, gr = tid & 3;
            cp16(cvta_s(&sB[st][row*48 + gr*8]), &Bw[(n0+row)*NC + k0 + gr*8], 16);
        }
    };

    float acc[2][4][4];
    #pragma unroll
    for (int i = 0; i < 2; i++)
        #pragma unroll
        for (int j = 0; j < 4; j++)
            #pragma unroll
            for (int c = 0; c < 4; c++) acc[i][j][c] = 0.f;

    load_stage(0, 0); CP_COMMIT();

    #pragma unroll 2
    for (int ch = 0; ch < 8; ch++) {
        const int cur = ch & 1;
        if (ch + 1 < 8) { load_stage(ch + 1, cur ^ 1); CP_COMMIT(); CP_WAIT1(); }
        else            { CP_WAIT0(); }
        __syncthreads();
        const __half* a = sA[cur];
        const __half* b = sB[cur];

        #pragma unroll
        for (int g2 = 0; g2 < 2; g2++) {
            uint32_t bf2[4][2];
            #pragma unroll
            for (int nt = 0; nt < 4; nt++) {
                const uint2 bv = *(const uint2*)&b[(wn + nt*8 + gID)*48 + g2*16 + tq*4];
                bf2[nt][0] = bv.x; bf2[nt][1] = bv.y;
            }
            #pragma unroll
            for (int mt = 0; mt < 2; mt++) {
                const __half* pa = &a[(wm + mt*16 + gID)*48 + g2*16 + tq*4];
                const uint2 a02 = *(const uint2*)pa;
                const uint2 a13 = *(const uint2*)&pa[8*48];
                uint32_t af[4] = { a02.x, a13.x, a02.y, a13.y };
                #pragma unroll
                for (int nt = 0; nt < 4; nt++)
                    mma_f16(acc[mt][nt], af, bf2[nt]);
            }
        }
        __syncthreads();
    }

    #pragma unroll
    for (int mt = 0; mt < 2; mt++) {
        #pragma unroll
        for (int half = 0; half < 2; half++) {
            const int t = m0 + wm + mt*16 + gID + half*8;
            #pragma unroll
            for (int nt = 0; nt < 4; nt++) {
                const int n = n0 + wn + nt*8 + tq*2;
                float v0 = acc[mt][nt][half*2 + 0];
                float v1 = acc[mt][nt][half*2 + 1];
                if (bias) { v0 += bias[n]; v1 += bias[n+1]; }
                if (!split) {
                    float2 v = { v0, v1 };
                    *(float2*)&outF[t*NC + n] = v;
                } else {
                    const int bb = t >> 10, tt = t & 1023;
                    const int h = n >> 5, d = n & 31;
                    if (z < 2) {
                        __half* dst = (z == 0) ? g_q16 : g_k16;
                        const int g = d >> 4, wd = (d & 15) >> 1;
                        const int off = ((bb*NH + h)*NL + tt)*HD + (g << 4) + (inv8(wd) << 1);
                        *(__half2*)&dst[off] = f2h2(v0, v1);
                    } else {
                        const int wt = (tt & 15) >> 1;
                        const int tp = (tt & ~15) | (inv8(wt) << 1) | (tt & 1);
                        const long base = (long)(bb*NH + h) * HD;
                        g_v16t[(base + d    )*NL + tp] = __float2half_rn(v0);
                        g_v16t[(base + d + 1)*NL + tp] = __float2half_rn(v1);
                    }
                }
            }
        }
    }
}

// ---------------------------------------------------------------------------
// fp16 tensor-core flash attention; fp32 softmax.
// Block = 128 threads (4 warps x 16 q rows). grid (64 bh, 16 q-tiles).
// K: [64 tok][32 dim-perm] stride 48; V^T: [32 dim][64 tok-perm] stride 80;
// P: [64 q][64 tok-perm half] stride 80. kt loop unrolled x2 (static buffers).
// ---------------------------------------------------------------------------
#define ARS 48
#define AVS 80
#define APS 80

__global__ __launch_bounds__(128) void attn16_kernel()
{
    extern __shared__ __half smh[];
    __half* sK[2]  = { smh, smh + 64*ARS };
    __half* sVt[2] = { smh + 2*64*ARS, smh + 2*64*ARS + 32*AVS };
    __half* sP     = smh + 2*64*ARS + 2*32*AVS;

    const int bh = blockIdx.x, qt = blockIdx.y;
    const int tid = threadIdx.x, w = tid >> 5, lane = tid & 31;
    const int gID = lane >> 2, tq = lane & 3;
    const int r0 = qt*64 + w*16;
    const __half* Qb = g_q16 + (long)bh*NL*HD;
    const __half* Kb = g_k16 + (long)bh*NL*HD;
    const __half* Vb = g_v16t + (long)bh*HD*NL;   // [32][1024]

    const __half2 sc2 = __floats2half2_rn(0.0625f, 0.0625f);
    uint32_t qf[2][4];
    #pragma unroll
    for (int g = 0; g < 2; g++) {
        uint2 lo = *(const uint2*)&Qb[(r0+gID  )*HD + g*16 + tq*4];
        uint2 hi = *(const uint2*)&Qb[(r0+gID+8)*HD + g*16 + tq*4];
        __half2 t;
        t = __hmul2(*(__half2*)&lo.x, sc2); qf[g][0] = *(uint32_t*)&t;
        t = __hmul2(*(__half2*)&hi.x, sc2); qf[g][1] = *(uint32_t*)&t;
        t = __hmul2(*(__half2*)&lo.y, sc2); qf[g][2] = *(uint32_t*)&t;
        t = __hmul2(*(__half2*)&hi.y, sc2); qf[g][3] = *(uint32_t*)&t;
    }

    float m0 = -1e30f, m1 = -1e30f, l0 = 0.f, l1 = 0.f;
    float oacc[4][4];
    #pragma unroll
    for (int i = 0; i < 4; i++)
        #pragma unroll
        for (int j = 0; j < 4; j++) oacc[i][j] = 0.f;

    auto load_kv = [&](int kt, int st) {
        #pragma unroll
        for (int u = 0; u < 2; u++) {
            const int q = u*128 + tid, row = q >> 2, gr = q & 3;
            cp16(cvta_s(&sK[st][row*ARS + gr*8]), &Kb[(kt*64 + row)*HD + gr*8], 16);
        }
        #pragma unroll
        for (int u = 0; u < 2; u++) {
            const int q = u*128 + tid, row = q >> 3, gr = q & 7;
            cp16(cvta_s(&sVt[st][row*AVS + gr*8]), &Vb[row*NL + kt*64 + gr*8], 16);
        }
    };

    load_kv(0, 0); CP_COMMIT();

    #pragma unroll 2
    for (int kt = 0; kt < 16; kt++) {
        const int cur = kt & 1;
        if (kt + 1 < 16) { load_kv(kt + 1, cur ^ 1); CP_COMMIT(); CP_WAIT1(); }
        else             { CP_WAIT0(); }
        __syncthreads();

        // S = Q K^T (16 x 64 per warp): 16 MMAs
        float sacc[8][4];
        #pragma unroll
        for (int nt = 0; nt < 8; nt++)
            #pragma unroll
            for (int c = 0; c < 4; c++) sacc[nt][c] = 0.f;
        #pragma unroll
        for (int g = 0; g < 2; g++) {
            #pragma unroll
            for (int nt = 0; nt < 8; nt++) {
                const uint2 bv = *(const uint2*)&sK[cur][(nt*8 + gID)*ARS + g*16 + tq*4];
                uint32_t bf[2] = { bv.x, bv.y };
                mma_f16(sacc[nt], qf[g], bf);
            }
        }

        // online softmax
        float mx0 = -1e30f, mx1 = -1e30f;
        #pragma unroll
        for (int nt = 0; nt < 8; nt++) {
            mx0 = fmaxf(mx0, fmaxf(sacc[nt][0], sacc[nt][1]));
            mx1 = fmaxf(mx1, fmaxf(sacc[nt][2], sacc[nt][3]));
        }
        mx0 = fmaxf(mx0, __shfl_xor_sync(~0u, mx0, 1));
        mx0 = fmaxf(mx0, __shfl_xor_sync(~0u, mx0, 2));
        mx1 = fmaxf(mx1, __shfl_xor_sync(~0u, mx1, 1));
        mx1 = fmaxf(mx1, __shfl_xor_sync(~0u, mx1, 2));
        const float mn0 = fmaxf(m0, mx0), mn1 = fmaxf(m1, mx1);
        const float c0 = __expf(m0 - mn0), c1 = __expf(m1 - mn1);

        float s0 = 0.f, s1 = 0.f;
        #pragma unroll
        for (int nt = 0; nt < 8; nt++) {
            float p0 = __expf(sacc[nt][0] - mn0);
            float p1 = __expf(sacc[nt][1] - mn0);
            float p2 = __expf(sacc[nt][2] - mn1);
            float p3 = __expf(sacc[nt][3] - mn1);
            s0 += p0 + p1; s1 += p2 + p3;
            const int colw = nt*8 + tq*2;
            const int po = ((colw >> 4) << 4) + inv8((colw & 15) >> 1)*2;
            *(__half2*)&sP[(w*16 + gID    )*APS + po] = f2h2(p0, p1);
            *(__half2*)&sP[(w*16 + gID + 8)*APS + po] = f2h2(p2, p3);
        }
        s0 += __shfl_xor_sync(~0u, s0, 1); s0 += __shfl_xor_sync(~0u, s0, 2);
        s1 += __shfl_xor_sync(~0u, s1, 1); s1 += __shfl_xor_sync(~0u, s1, 2);
        l0 = l0*c0 + s0; l1 = l1*c1 + s1;
        #pragma unroll
        for (int nt = 0; nt < 4; nt++) {
            oacc[nt][0] *= c0; oacc[nt][1] *= c0;
            oacc[nt][2] *= c1; oacc[nt][3] *= c1;
        }
        m0 = mn0; m1 = mn1;
        __syncwarp();

        // O += P V : 16 MMAs
        #pragma unroll
        for (int ks = 0; ks < 4; ks++) {
            const __half* prow = &sP[(w*16 + gID)*APS + ks*16 + tq*4];
            const uint2 a02 = *(const uint2*)prow;
            const uint2 a13 = *(const uint2*)&prow[8*APS];
            uint32_t pa[4] = { a02.x, a13.x, a02.y, a13.y };
            #pragma unroll
            for (int nt = 0; nt < 4; nt++) {
                const uint2 bv = *(const uint2*)&sVt[cur][(nt*8 + gID)*AVS + ks*16 + tq*4];
                uint32_t vb[2] = { bv.x, bv.y };
                mma_f16(oacc[nt], pa, vb);
            }
        }
        __syncthreads();
    }

    const float i0 = 1.f / l0, i1 = 1.f / l1;
    const int b = bh >> 3, h = bh & 7;
    #pragma unroll
    for (int nt = 0; nt < 4; nt++) {
        const int ch = h*HD + nt*8 + tq*2;
        const int off = ((ch >> 4) << 4) + inv8((ch & 15) >> 1)*2;
        *(__half2*)&g_ao16[(b*NL + r0 + gID    )*NC + off] =
            f2h2(oacc[nt][0]*i0, oacc[nt][1]*i0);
        *(__half2*)&g_ao16[(b*NL + r0 + gID + 8)*NC + off] =
            f2h2(oacc[nt][2]*i1, oacc[nt][3]*i1);
    }
}

// ------------------------ small prep / stats kernels ------------------------
__global__ __launch_bounds__(256) void cvt_xy_kernel(
    const float* __restrict__ x, const float* __restrict__ y)
{
    const float* s = blockIdx.y ? y : x;
    __half* d = blockIdx.y ? g_y16 : g_x16;
    const int base = (blockIdx.x * 256 + threadIdx.x) * 8;
    const int token = base >> 8;
    const int cs0 = base & 255;
    __half tmp[8];
    #pragma unroll
    for (int jj = 0; jj < 8; jj++)
        tmp[jj] = __float2half_rn(s[token*NC + orig_ch(cs0 + jj)]);
    *(uint4*)&d[base] = *(const uint4*)tmp;
}

__global__ __launch_bounds__(256) void round_wo_kernel(const float* __restrict__ Wo)
{
    const int idx = blockIdx.x * 256 + threadIdx.x;   // co*256 + storage ci
    const int ci = idx & 255, co = idx >> 8;
    g_wo16[idx] = __float2half_rn(Wo[co*NC + orig_ch(ci)]);
}

__global__ __launch_bounds__(256) void wtrans_kernel(
    const float* __restrict__ wq, const float* __restrict__ wk,
    const float* __restrict__ wv)
{
    const float* W = (blockIdx.y == 0) ? wq : (blockIdx.y == 1) ? wk : wv;
    __half* dst = g_wt16 + (long)blockIdx.y * 9*NC*NC;
    const int idx = blockIdx.x * 256 + threadIdx.x;
    const int ci  = idx & 255;
    const int rem = idx >> 8;
    const int co  = rem & 255;
    const int tap = rem >> 8;
    dst[idx] = __float2half_rn(W[(co*NC + orig_ch(ci))*9 + tap]);
}

__global__ __launch_bounds__(256) void stats_partial_kernel()
{
    const __half* src = g_cv16 + (long)blockIdx.y * NT*NC;
    const int c = threadIdx.x;
    float s = 0.f, s2 = 0.f;
    const int t0 = blockIdx.x * (NT/64);
    #pragma unroll 4
    for (int t = t0; t < t0 + NT/64; t++) {
        float val = __half2float(src[t*NC + c]);
        s += val; s2 += val*val;
    }
    g_part[((blockIdx.y*64 + blockIdx.x)*2 + 0)*NC + c] = s;
    g_part[((blockIdx.y*64 + blockIdx.x)*2 + 1)*NC + c] = s2;
}

__global__ __launch_bounds__(1024) void stats_final_kernel(
    const float* __restrict__ gq, const float* __restrict__ bq,
    const float* __restrict__ gk, const float* __restrict__ bk,
    const float* __restrict__ gv, const float* __restrict__ bv)
{
    const int s = blockIdx.x;
    const int c = threadIdx.x & 255;        // storage channel
    const int seg = threadIdx.x >> 8;
    float sum = 0.f, sum2 = 0.f;
    #pragma unroll
    for (int i = seg*16; i < seg*16 + 16; i++) {
        sum  += g_part[((s*64+i)*2 + 0)*NC + c];
        sum2 += g_part[((s*64+i)*2 + 1)*NC + c];
    }
    __shared__ float red[8][256];
    red[seg][c] = sum; red[4+seg][c] = sum2;
    __syncthreads();
    if (seg == 0) {
        sum  = red[0][c] + red[1][c] + red[2][c] + red[3][c];
        sum2 = red[4][c] + red[5][c] + red[6][c] + red[7][c];
        float mu  = sum  * (1.f/NT);
        float var = sum2 * (1.f/NT) - mu*mu;
        const float* gam = (s == 0) ? gq : (s == 1) ? gk : gv;
        const float* bet = (s == 0) ? bq : (s == 1) ? bk : bv;
        const int oc = orig_ch(c);
        float a  = gam[oc] * rsqrtf(var + 1e-5f);
        float bb = bet[oc] - mu*a;
        g_ab[(s*2+0)*NC + c] = a;
        g_ab[(s*2+1)*NC + c] = bb;
    }
}

__global__ __launch_bounds__(256) void fold_kernel(
    const float* __restrict__ Wq, const float* __restrict__ Wk,
    const float* __restrict__ Wv)
{
    const int s  = blockIdx.y;
    const int co = blockIdx.x;
    const int c  = threadIdx.x;            // storage channel
    const float* W = (s == 0) ? Wq : (s == 1) ? Wk : Wv;
    float a  = g_ab[(s*2+0)*NC + c];
    float bb = g_ab[(s*2+1)*NC + c];
    float wv = W[co*NC + orig_ch(c)];
    g_wf16[s*NC*NC + co*NC + c] = __float2half_rn(wv * a);

    __shared__ float red[256];
    red[c] = wv * bb;
    __syncthreads();
    for (int o = 128; o > 0; o >>= 1) {
        if (c < o) red[c] += red[c + o];
        __syncthreads();
    }
    if (c == 0) g_bf[s*NC + co] = red[0];
}

// ---------------------------------------------------------------------------

extern "C" void kernel_launch(void* const* d_in, const int* in_sizes, int n_in,
                              void* d_out, int out_size)
{
    const float* x        = (const float*)d_in[0];
    const float* y        = (const float*)d_in[1];
    const float* conv_q_w = (const float*)d_in[4];
    const float* bn_q_g   = (const float*)d_in[5];
    const float* bn_q_b   = (const float*)d_in[6];
    const float* conv_k_w = (const float*)d_in[7];
    const float* bn_k_g   = (const float*)d_in[8];
    const float* bn_k_b   = (const float*)d_in[9];
    const float* conv_v_w = (const float*)d_in[10];
    const float* bn_v_g   = (const float*)d_in[11];
    const float* bn_v_b   = (const float*)d_in[12];
    const float* Wq       = (const float*)d_in[13];
    const float* Wk       = (const float*)d_in[14];
    const float* Wv       = (const float*)d_in[15];
    const float* Wo       = (const float*)d_in[16];
    const float* bo       = (const float*)d_in[17];
    float* out = (float*)d_out;

    __half *cv16, *wf16, *ao16, *wo16;
    float *bf;
    cudaGetSymbolAddress((void**)&cv16, g_cv16);
    cudaGetSymbolAddress((void**)&wf16, g_wf16);
    cudaGetSymbolAddress((void**)&ao16, g_ao16);
    cudaGetSymbolAddress((void**)&wo16, g_wo16);
    cudaGetSymbolAddress((void**)&bf, g_bf);

    const int CONV_SMEM  = (CONV_A_H + CONV_B_H) * 2 * 2;         // 49920 B
    const int GEMM_SMEM  = (6144 + 3072) * 2 * 2;                 // 36864 B
    const int ATTN_SMEM  = (2*64*ARS + 2*32*AVS + 64*APS) * 2;    // 32768 B
    cudaFuncSetAttribute(conv_gemm_kernel,
                         cudaFuncAttributeMaxDynamicSharedMemorySize, CONV_SMEM);
    cudaFuncSetAttribute(gemm16_kernel,
                         cudaFuncAttributeMaxDynamicSharedMemorySize, GEMM_SMEM);
    cudaFuncSetAttribute(attn16_kernel,
                         cudaFuncAttributeMaxDynamicSharedMemorySize, ATTN_SMEM);

    // operand conversion + permuted weight layouts
    cvt_xy_kernel<<<dim3(NT*NC/2048, 2), 256>>>(x, y);
    wtrans_kernel<<<dim3(9*NC, 3), 256>>>(conv_q_w, conv_k_w, conv_v_w);
    round_wo_kernel<<<NC*NC/256, 256>>>(Wo);

    // 3 convs, halo implicit GEMM on fp16 tensor cores -> fp16 permuted output
    conv_gemm_kernel<<<dim3(NT/128, NC/64, 3), 256, CONV_SMEM>>>();

    // BN stats -> fold into fp16 projection weights
    stats_partial_kernel<<<dim3(64, 3), 256>>>();
    stats_final_kernel<<<3, 1024>>>(bn_q_g, bn_q_b, bn_k_g, bn_k_b, bn_v_g, bn_v_b);
    fold_kernel<<<dim3(NC, 3), 256>>>(Wq, Wk, Wv);

    // 3 projections (fp16): Q/K dim-permuted, V transposed token-permuted
    gemm16_kernel<<<dim3(NT/128, NC/64, 3), 256, GEMM_SMEM>>>(
        cv16, cv16 + (long)NT*NC, cv16 + (long)2*NT*NC,
        wf16, (long)NC*NC, bf, nullptr, 1);

    // fp16 flash attention
    attn16_kernel<<<dim3(NB*NH, NL/64), 128, ATTN_SMEM>>>();

    // output projection (fp16 GEMM, fp32 natural output)
    gemm16_kernel<<<dim3(NT/128, NC/64, 1), 256, GEMM_SMEM>>>(
        ao16, ao16, ao16, wo16, 0, bo, out, 0);
}

// round 15
// speedup vs baseline: 1.4437x; 1.0291x over previous
#include <cuda_runtime.h>
#include <cuda_fp16.h>
#include <math.h>
#include <cstdint>

#define NB 8
#define NL 1024
#define NC 256
#define NH 8
#define HD 32
#define NT (NB*NL)   /* 8192 tokens */

// ------------------------- scratch (device globals) -------------------------
static __device__ __align__(16) __half g_x16[NT*NC];      // fp16 x, natural ci
static __device__ __align__(16) __half g_y16[NT*NC];      // fp16 y, natural ci
static __device__ __align__(16) __half g_wt16[3*9*NC*NC]; // conv w [conv][tap][co][ci] natural
static __device__ __align__(16) __half g_cv16[3*NT*NC];   // conv out, word-permuted ch
static __device__ __align__(16) __half g_q16[NT*NC];      // Q [bh][L][32] dim-perm
static __device__ __align__(16) __half g_k16[NT*NC];      // K [bh][L][32] dim-perm
static __device__ __align__(16) __half g_v16t[NT*NC];     // V^T [bh][32][L] tok-perm
static __device__ __align__(16) __half g_ao16[NT*NC];     // attn out [t][256] ch-perm
static __device__ __align__(16) __half g_wf16[3*NC*NC];   // folded proj w, ci-perm
static __device__ __align__(16) __half g_wo16[NC*NC];     // Wo fp16, ci-perm
static __device__ float g_part[3*64*2*NC];
static __device__ float g_ab[3*2*NC];
static __device__ float g_bf[3*NC];

// ------------------------------ helpers -------------------------------------
__device__ __forceinline__ uint32_t cvta_s(const void* p) {
    return (uint32_t)__cvta_generic_to_shared(p);
}
__device__ __forceinline__ void cp16(uint32_t d, const void* s, uint32_t sz) {
    asm volatile("cp.async.cg.shared.global [%0], [%1], 16, %2;"
                 :: "r"(d), "l"(s), "r"(sz));
}
#define CP_COMMIT() asm volatile("cp.async.commit_group;")
#define CP_WAIT1()  asm volatile("cp.async.wait_group 1;")
#define CP_WAIT0()  asm volatile("cp.async.wait_group 0;")

__device__ __forceinline__ void mma_f16(float* c, const uint32_t* a, const uint32_t* b) {
    asm volatile(
        "mma.sync.aligned.m16n8k16.row.col.f32.f16.f16.f32 "
        "{%0,%1,%2,%3}, {%4,%5,%6,%7}, {%8,%9}, {%0,%1,%2,%3};"
        : "+f"(c[0]), "+f"(c[1]), "+f"(c[2]), "+f"(c[3])
        : "r"(a[0]), "r"(a[1]), "r"(a[2]), "r"(a[3]), "r"(b[0]), "r"(b[1]));
}
__device__ __forceinline__ void ldsm_x4(uint32_t& r0, uint32_t& r1,
                                        uint32_t& r2, uint32_t& r3, uint32_t addr) {
    asm volatile("ldmatrix.sync.aligned.m8n8.x4.shared.b16 {%0,%1,%2,%3}, [%4];"
                 : "=r"(r0), "=r"(r1), "=r"(r2), "=r"(r3) : "r"(addr));
}

// word permutation within each 8-word (16-channel) group (used downstream only)
__device__ __forceinline__ int perm8(int j) { return ((j & 1) << 2) | (j >> 1); }
__device__ __forceinline__ int inv8(int w)  { return ((w & 3) << 1) | (w >> 2); }
__device__ __forceinline__ int orig_ch(int s) {
    return (s & ~15) | (perm8((s & 15) >> 1) << 1) | (s & 1);
}
__device__ __forceinline__ __half2 f2h2(float a, float b) {
    return __floats2half2_rn(a, b);
}

// ---------------------------------------------------------------------------
// Implicit 3x3 conv on fp16 tensor cores (m16n8k16), halo smem + ldmatrix.
// Tile M=128 tokens x N=64 co; 8 warps (4m x 2n), warp 32x32.
// K-loop: 16 ci-chunks of 16. smem rows stride 24 halves (48B): ldmatrix
// phases hit banks 12j mod 32 = all distinct -> conflict-free.
// A frag: 1 ldmatrix.x4; B frag pair: 1 ldmatrix.x4 (4 LDSM + 8 MMA per tap).
// Output fp16, channel-word-permuted (downstream unchanged).
// ---------------------------------------------------------------------------
#define CRS 24                     /* smem row stride in halves */
#define CONV_A_H (204*CRS)         /* 4896 */
#define CONV_B_H (576*CRS)         /* 13824 */
#define CONV_NCH 16

__global__ __launch_bounds__(256, 3) void conv_gemm_kernel()
{
    extern __shared__ __half smh[];
    __half* sA[2] = { smh, smh + CONV_A_H };
    __half* sB[2] = { smh + 2*CONV_A_H, smh + 2*CONV_A_H + CONV_B_H };
    const uint32_t aB[2] = { cvta_s(sA[0]), cvta_s(sA[1]) };
    const uint32_t bB[2] = { cvta_s(sB[0]), cvta_s(sB[1]) };

    const int z = blockIdx.z;
    const __half* Ain = (z == 0) ? g_x16 : g_y16;
    const __half* Wtz = g_wt16 + (long)z * 9*NC*NC;
    __half* outh = g_cv16 + (long)z * NT*NC;

    const int tid = threadIdx.x;
    const int wid = tid >> 5, lane = tid & 31;
    const int gID = lane >> 2, tq = lane & 3;
    const int l7 = lane & 7, b3 = (lane >> 3) & 1, b4 = (lane >> 4) & 1;
    const int wm = (wid >> 1) * 32, wn = (wid & 1) * 32;
    const int m0 = blockIdx.x * 128, n0 = blockIdx.y * 64;
    const int bImg = blockIdx.x >> 3;
    const int r0b  = (blockIdx.x & 7) * 4;

    // per-thread ldmatrix base offsets (bytes), loop-invariant
    const uint32_t aOff = (uint32_t)(((b3*8 + l7)*CRS + b4*8) * 2);
    const uint32_t bOff = (uint32_t)(((wn + b4*8 + l7)*CRS + b3*8) * 2);

    auto load_stage = [&](int cc, int st) {
        const int ci0 = cc * 16;
        for (int q = tid; q < 408; q += 256) {
            const int cell = q >> 1, h8 = q & 1;
            const int hr = cell / 34, hc = cell - hr*34;
            const int ir = r0b + hr - 1, ic = hc - 1;
            const bool ok = ((unsigned)ir < 32u) && ((unsigned)ic < 32u);
            const __half* src = ok ? &Ain[((bImg<<10) + ir*32 + ic)*NC + ci0 + h8*8]
                                   : Ain;
            cp16(cvta_s(&sA[st][cell*CRS + h8*8]), src, ok ? 16 : 0);
        }
        for (int q = tid; q < 1152; q += 256) {
            const int rowc = q >> 1, h8 = q & 1;
            const int tap = rowc >> 6, co = rowc & 63;
            const __half* src = &Wtz[((tap<<8) + n0 + co)*NC + ci0 + h8*8];
            cp16(cvta_s(&sB[st][rowc*CRS + h8*8]), src, 16);
        }
    };

    float acc[2][4][4];
    #pragma unroll
    for (int i = 0; i < 2; i++)
        #pragma unroll
        for (int j = 0; j < 4; j++)
            #pragma unroll
            for (int c = 0; c < 4; c++) acc[i][j][c] = 0.f;

    load_stage(0, 0); CP_COMMIT();

    #pragma unroll 2
    for (int cc = 0; cc < CONV_NCH; cc++) {
        const int cur = cc & 1;
        if (cc + 1 < CONV_NCH) { load_stage(cc + 1, cur ^ 1); CP_COMMIT(); CP_WAIT1(); }
        else                   { CP_WAIT0(); }
        __syncthreads();
        const uint32_t aBase = aB[cur];
        const uint32_t bBase = bB[cur];

        #pragma unroll
        for (int tap = 0; tap < 9; tap++) {
            const int d3 = tap / 3, m3 = tap - d3*3;
            // B fragments: nt 0..3 via 2 ldmatrix.x4
            uint32_t bfr[8];
            ldsm_x4(bfr[0], bfr[1], bfr[2], bfr[3],
                    bBase + bOff + (uint32_t)(tap*64*CRS*2));
            ldsm_x4(bfr[4], bfr[5], bfr[6], bfr[7],
                    bBase + bOff + (uint32_t)((tap*64 + 16)*CRS*2));
            #pragma unroll
            for (int mt = 0; mt < 2; mt++) {
                const int base = wm + mt*16;
                const int cbm = ((base >> 5) + d3)*34 + (base & 31) + m3;
                uint32_t af[4];
                ldsm_x4(af[0], af[1], af[2], af[3],
                        aBase + aOff + (uint32_t)(cbm*CRS*2));
                #pragma unroll
                for (int nt = 0; nt < 4; nt++)
                    mma_f16(acc[mt][nt], af, &bfr[nt*2]);
            }
        }
        __syncthreads();
    }

    #pragma unroll
    for (int mt = 0; mt < 2; mt++) {
        #pragma unroll
        for (int half = 0; half < 2; half++) {
            const int t = m0 + wm + mt*16 + gID + half*8;
            #pragma unroll
            for (int nt = 0; nt < 4; nt++) {
                const int n = n0 + wn + nt*8 + tq*2;
                const int g = n >> 4, wd = (n & 15) >> 1;
                const int off = t*NC + (g << 4) + (inv8(wd) << 1);
                *(__half2*)&outh[off] = f2h2(acc[mt][nt][half*2 + 0],
                                             acc[mt][nt][half*2 + 1]);
            }
        }
    }
}

// ---------------------------------------------------------------------------
// Unified fp16 tensor-core GEMM (unchanged from R14): word-permuted operands.
// ---------------------------------------------------------------------------
__global__ __launch_bounds__(256) void gemm16_kernel(
    const __half* __restrict__ A0, const __half* __restrict__ A1,
    const __half* __restrict__ A2,
    const __half* __restrict__ B0, long bStride,
    const float* __restrict__ bias0, float* __restrict__ outF, int split)
{
    extern __shared__ __half smh[];
    __half* sA[2] = { smh, smh + 6144 };
    __half* sB[2] = { smh + 12288, smh + 12288 + 3072 };

    const int z = blockIdx.z;
    const __half* A  = (z == 0) ? A0 : ((z == 1) ? A1 : A2);
    const __half* Bw = B0 + (long)z * bStride;
    const float* bias = bias0 ? (bias0 + z*NC) : nullptr;

    const int tid = threadIdx.x;
    const int wid = tid >> 5, lane = tid & 31;
    const int gID = lane >> 2, tq = lane & 3;
    const int wm = (wid >> 1) * 32, wn = (wid & 1) * 32;
    const int m0 = blockIdx.x * 128, n0 = blockIdx.y * 64;

    auto load_stage = [&](int ch, int st) {
        const int k0 = ch * 32;
        #pragma unroll
        for (int u = 0; u < 2; u++) {
            const int q = u*256 + tid, row = q >> 2, gr = q & 3;
            cp16(cvta_s(&sA[st][row*48 + gr*8]), &A[(m0+row)*NC + k0 + gr*8], 16);
        }
        {
            const int row = tid >> 2, gr = tid & 3;
            cp16(cvta_s(&sB[st][row*48 + gr*8]), &Bw[(n0+row)*NC + k0 + gr*8], 16);
        }
    };

    float acc[2][4][4];
    #pragma unroll
    for (int i = 0; i < 2; i++)
        #pragma unroll
        for (int j = 0; j < 4; j++)
            #pragma unroll
            for (int c = 0; c < 4; c++) acc[i][j][c] = 0.f;

    load_stage(0, 0); CP_COMMIT();

    #pragma unroll 2
    for (int ch = 0; ch < 8; ch++) {
        const int cur = ch & 1;
        if (ch + 1 < 8) { load_stage(ch + 1, cur ^ 1); CP_COMMIT(); CP_WAIT1(); }
        else            { CP_WAIT0(); }
        __syncthreads();
        const __half* a = sA[cur];
        const __half* b = sB[cur];

        #pragma unroll
        for (int g2 = 0; g2 < 2; g2++) {
            uint32_t bf2[4][2];
            #pragma unroll
            for (int nt = 0; nt < 4; nt++) {
                const uint2 bv = *(const uint2*)&b[(wn + nt*8 + gID)*48 + g2*16 + tq*4];
                bf2[nt][0] = bv.x; bf2[nt][1] = bv.y;
            }
            #pragma unroll
            for (int mt = 0; mt < 2; mt++) {
                const __half* pa = &a[(wm + mt*16 + gID)*48 + g2*16 + tq*4];
                const uint2 a02 = *(const uint2*)pa;
                const uint2 a13 = *(const uint2*)&pa[8*48];
                uint32_t af[4] = { a02.x, a13.x, a02.y, a13.y };
                #pragma unroll
                for (int nt = 0; nt < 4; nt++)
                    mma_f16(acc[mt][nt], af, bf2[nt]);
            }
        }
        __syncthreads();
    }

    #pragma unroll
    for (int mt = 0; mt < 2; mt++) {
        #pragma unroll
        for (int half = 0; half < 2; half++) {
            const int t = m0 + wm + mt*16 + gID + half*8;
            #pragma unroll
            for (int nt = 0; nt < 4; nt++) {
                const int n = n0 + wn + nt*8 + tq*2;
                float v0 = acc[mt][nt][half*2 + 0];
                float v1 = acc[mt][nt][half*2 + 1];
                if (bias) { v0 += bias[n]; v1 += bias[n+1]; }
                if (!split) {
                    float2 v = { v0, v1 };
                    *(float2*)&outF[t*NC + n] = v;
                } else {
                    const int bb = t >> 10, tt = t & 1023;
                    const int h = n >> 5, d = n & 31;
                    if (z < 2) {
                        __half* dst = (z == 0) ? g_q16 : g_k16;
                        const int g = d >> 4, wd = (d & 15) >> 1;
                        const int off = ((bb*NH + h)*NL + tt)*HD + (g << 4) + (inv8(wd) << 1);
                        *(__half2*)&dst[off] = f2h2(v0, v1);
                    } else {
                        const int wt = (tt & 15) >> 1;
                        const int tp = (tt & ~15) | (inv8(wt) << 1) | (tt & 1);
                        const long base = (long)(bb*NH + h) * HD;
                        g_v16t[(base + d    )*NL + tp] = __float2half_rn(v0);
                        g_v16t[(base + d + 1)*NL + tp] = __float2half_rn(v1);
                    }
                }
            }
        }
    }
}

// ---------------------------------------------------------------------------
// fp16 tensor-core flash attention (unchanged from R14).
// ---------------------------------------------------------------------------
#define ARS 48
#define AVS 80
#define APS 80

__global__ __launch_bounds__(128) void attn16_kernel()
{
    extern __shared__ __half smh[];
    __half* sK[2]  = { smh, smh + 64*ARS };
    __half* sVt[2] = { smh + 2*64*ARS, smh + 2*64*ARS + 32*AVS };
    __half* sP     = smh + 2*64*ARS + 2*32*AVS;

    const int bh = blockIdx.x, qt = blockIdx.y;
    const int tid = threadIdx.x, w = tid >> 5, lane = tid & 31;
    const int gID = lane >> 2, tq = lane & 3;
    const int r0 = qt*64 + w*16;
    const __half* Qb = g_q16 + (long)bh*NL*HD;
    const __half* Kb = g_k16 + (long)bh*NL*HD;
    const __half* Vb = g_v16t + (long)bh*HD*NL;

    const __half2 sc2 = __floats2half2_rn(0.0625f, 0.0625f);
    uint32_t qf[2][4];
    #pragma unroll
    for (int g = 0; g < 2; g++) {
        uint2 lo = *(const uint2*)&Qb[(r0+gID  )*HD + g*16 + tq*4];
        uint2 hi = *(const uint2*)&Qb[(r0+gID+8)*HD + g*16 + tq*4];
        __half2 t;
        t = __hmul2(*(__half2*)&lo.x, sc2); qf[g][0] = *(uint32_t*)&t;
        t = __hmul2(*(__half2*)&hi.x, sc2); qf[g][1] = *(uint32_t*)&t;
        t = __hmul2(*(__half2*)&lo.y, sc2); qf[g][2] = *(uint32_t*)&t;
        t = __hmul2(*(__half2*)&hi.y, sc2); qf[g][3] = *(uint32_t*)&t;
    }

    float m0 = -1e30f, m1 = -1e30f, l0 = 0.f, l1 = 0.f;
    float oacc[4][4];
    #pragma unroll
    for (int i = 0; i < 4; i++)
        #pragma unroll
        for (int j = 0; j < 4; j++) oacc[i][j] = 0.f;

    auto load_kv = [&](int kt, int st) {
        #pragma unroll
        for (int u = 0; u < 2; u++) {
            const int q = u*128 + tid, row = q >> 2, gr = q & 3;
            cp16(cvta_s(&sK[st][row*ARS + gr*8]), &Kb[(kt*64 + row)*HD + gr*8], 16);
        }
        #pragma unroll
        for (int u = 0; u < 2; u++) {
            const int q = u*128 + tid, row = q >> 3, gr = q & 7;
            cp16(cvta_s(&sVt[st][row*AVS + gr*8]), &Vb[row*NL + kt*64 + gr*8], 16);
        }
    };

    load_kv(0, 0); CP_COMMIT();

    #pragma unroll 2
    for (int kt = 0; kt < 16; kt++) {
        const int cur = kt & 1;
        if (kt + 1 < 16) { load_kv(kt + 1, cur ^ 1); CP_COMMIT(); CP_WAIT1(); }
        else             { CP_WAIT0(); }
        __syncthreads();

        float sacc[8][4];
        #pragma unroll
        for (int nt = 0; nt < 8; nt++)
            #pragma unroll
            for (int c = 0; c < 4; c++) sacc[nt][c] = 0.f;
        #pragma unroll
        for (int g = 0; g < 2; g++) {
            #pragma unroll
            for (int nt = 0; nt < 8; nt++) {
                const uint2 bv = *(const uint2*)&sK[cur][(nt*8 + gID)*ARS + g*16 + tq*4];
                uint32_t bf[2] = { bv.x, bv.y };
                mma_f16(sacc[nt], qf[g], bf);
            }
        }

        float mx0 = -1e30f, mx1 = -1e30f;
        #pragma unroll
        for (int nt = 0; nt < 8; nt++) {
            mx0 = fmaxf(mx0, fmaxf(sacc[nt][0], sacc[nt][1]));
            mx1 = fmaxf(mx1, fmaxf(sacc[nt][2], sacc[nt][3]));
        }
        mx0 = fmaxf(mx0, __shfl_xor_sync(~0u, mx0, 1));
        mx0 = fmaxf(mx0, __shfl_xor_sync(~0u, mx0, 2));
        mx1 = fmaxf(mx1, __shfl_xor_sync(~0u, mx1, 1));
        mx1 = fmaxf(mx1, __shfl_xor_sync(~0u, mx1, 2));
        const float mn0 = fmaxf(m0, mx0), mn1 = fmaxf(m1, mx1);
        const float c0 = __expf(m0 - mn0), c1 = __expf(m1 - mn1);

        float s0 = 0.f, s1 = 0.f;
        #pragma unroll
        for (int nt = 0; nt < 8; nt++) {
            float p0 = __expf(sacc[nt][0] - mn0);
            float p1 = __expf(sacc[nt][1] - mn0);
            float p2 = __expf(sacc[nt][2] - mn1);
            float p3 = __expf(sacc[nt][3] - mn1);
            s0 += p0 + p1; s1 += p2 + p3;
            const int colw = nt*8 + tq*2;
            const int po = ((colw >> 4) << 4) + inv8((colw & 15) >> 1)*2;
            *(__half2*)&sP[(w*16 + gID    )*APS + po] = f2h2(p0, p1);
            *(__half2*)&sP[(w*16 + gID + 8)*APS + po] = f2h2(p2, p3);
        }
        s0 += __shfl_xor_sync(~0u, s0, 1); s0 += __shfl_xor_sync(~0u, s0, 2);
        s1 += __shfl_xor_sync(~0u, s1, 1); s1 += __shfl_xor_sync(~0u, s1, 2);
        l0 = l0*c0 + s0; l1 = l1*c1 + s1;
        #pragma unroll
        for (int nt = 0; nt < 4; nt++) {
            oacc[nt][0] *= c0; oacc[nt][1] *= c0;
            oacc[nt][2] *= c1; oacc[nt][3] *= c1;
        }
        m0 = mn0; m1 = mn1;
        __syncwarp();

        #pragma unroll
        for (int ks = 0; ks < 4; ks++) {
            const __half* prow = &sP[(w*16 + gID)*APS + ks*16 + tq*4];
            const uint2 a02 = *(const uint2*)prow;
            const uint2 a13 = *(const uint2*)&prow[8*APS];
            uint32_t pa[4] = { a02.x, a13.x, a02.y, a13.y };
            #pragma unroll
            for (int nt = 0; nt < 4; nt++) {
                const uint2 bv = *(const uint2*)&sVt[cur][(nt*8 + gID)*AVS + ks*16 + tq*4];
                uint32_t vb[2] = { bv.x, bv.y };
                mma_f16(oacc[nt], pa, vb);
            }
        }
        __syncthreads();
    }

    const float i0 = 1.f / l0, i1 = 1.f / l1;
    const int b = bh >> 3, h = bh & 7;
    #pragma unroll
    for (int nt = 0; nt < 4; nt++) {
        const int ch = h*HD + nt*8 + tq*2;
        const int off = ((ch >> 4) << 4) + inv8((ch & 15) >> 1)*2;
        *(__half2*)&g_ao16[(b*NL + r0 + gID    )*NC + off] =
            f2h2(oacc[nt][0]*i0, oacc[nt][1]*i0);
        *(__half2*)&g_ao16[(b*NL + r0 + gID + 8)*NC + off] =
            f2h2(oacc[nt][2]*i1, oacc[nt][3]*i1);
    }
}

// ------------------------ small prep / stats kernels ------------------------
// x/y -> fp16, NATURAL channel order (conv now uses ldmatrix)
__global__ __launch_bounds__(256) void cvt_xy_kernel(
    const float* __restrict__ x, const float* __restrict__ y)
{
    const float* s = blockIdx.y ? y : x;
    __half* d = blockIdx.y ? g_y16 : g_x16;
    const int base = (blockIdx.x * 256 + threadIdx.x) * 8;
    float4 v0 = *(const float4*)(s + base);
    float4 v1 = *(const float4*)(s + base + 4);
    __half2 h[4] = { f2h2(v0.x, v0.y), f2h2(v0.z, v0.w),
                     f2h2(v1.x, v1.y), f2h2(v1.z, v1.w) };
    *(uint4*)&d[base] = *(const uint4*)h;
}

__global__ __launch_bounds__(256) void round_wo_kernel(const float* __restrict__ Wo)
{
    const int idx = blockIdx.x * 256 + threadIdx.x;   // co*256 + storage ci
    const int ci = idx & 255, co = idx >> 8;
    g_wo16[idx] = __float2half_rn(Wo[co*NC + orig_ch(ci)]);
}

// conv weights -> fp16 [conv][tap][co][ci], NATURAL ci order
__global__ __launch_bounds__(256) void wtrans_kernel(
    const float* __restrict__ wq, const float* __restrict__ wk,
    const float* __restrict__ wv)
{
    const float* W = (blockIdx.y == 0) ? wq : (blockIdx.y == 1) ? wk : wv;
    __half* dst = g_wt16 + (long)blockIdx.y * 9*NC*NC;
    const int idx = blockIdx.x * 256 + threadIdx.x;
    const int ci  = idx & 255;
    const int rem = idx >> 8;
    const int co  = rem & 255;
    const int tap = rem >> 8;
    dst[idx] = __float2half_rn(W[(co*NC + ci)*9 + tap]);
}

__global__ __launch_bounds__(256) void stats_partial_kernel()
{
    const __half* src = g_cv16 + (long)blockIdx.y * NT*NC;
    const int c = threadIdx.x;
    float s = 0.f, s2 = 0.f;
    const int t0 = blockIdx.x * (NT/64);
    #pragma unroll 4
    for (int t = t0; t < t0 + NT/64; t++) {
        float val = __half2float(src[t*NC + c]);
        s += val; s2 += val*val;
    }
    g_part[((blockIdx.y*64 + blockIdx.x)*2 + 0)*NC + c] = s;
    g_part[((blockIdx.y*64 + blockIdx.x)*2 + 1)*NC + c] = s2;
}

__global__ __launch_bounds__(1024) void stats_final_kernel(
    const float* __restrict__ gq, const float* __restrict__ bq,
    const float* __restrict__ gk, const float* __restrict__ bk,
    const float* __restrict__ gv, const float* __restrict__ bv)
{
    const int s = blockIdx.x;
    const int c = threadIdx.x & 255;        // storage channel
    const int seg = threadIdx.x >> 8;
    float sum = 0.f, sum2 = 0.f;
    #pragma unroll
    for (int i = seg*16; i < seg*16 + 16; i++) {
        sum  += g_part[((s*64+i)*2 + 0)*NC + c];
        sum2 += g_part[((s*64+i)*2 + 1)*NC + c];
    }
    __shared__ float red[8][256];
    red[seg][c] = sum; red[4+seg][c] = sum2;
    __syncthreads();
    if (seg == 0) {
        sum  = red[0][c] + red[1][c] + red[2][c] + red[3][c];
        sum2 = red[4][c] + red[5][c] + red[6][c] + red[7][c];
        float mu  = sum  * (1.f/NT);
        float var = sum2 * (1.f/NT) - mu*mu;
        const float* gam = (s == 0) ? gq : (s == 1) ? gk : gv;
        const float* bet = (s == 0) ? bq : (s == 1) ? bk : bv;
        const int oc = orig_ch(c);
        float a  = gam[oc] * rsqrtf(var + 1e-5f);
        float bb = bet[oc] - mu*a;
        g_ab[(s*2+0)*NC + c] = a;
        g_ab[(s*2+1)*NC + c] = bb;
    }
}

__global__ __launch_bounds__(256) void fold_kernel(
    const float* __restrict__ Wq, const float* __restrict__ Wk,
    const float* __restrict__ Wv)
{
    const int s  = blockIdx.y;
    const int co = blockIdx.x;
    const int c  = threadIdx.x;            // storage channel
    const float* W = (s == 0) ? Wq : (s == 1) ? Wk : Wv;
    float a  = g_ab[(s*2+0)*NC + c];
    float bb = g_ab[(s*2+1)*NC + c];
    float wv = W[co*NC + orig_ch(c)];
    g_wf16[s*NC*NC + co*NC + c] = __float2half_rn(wv * a);

    __shared__ float red[256];
    red[c] = wv * bb;
    __syncthreads();
    for (int o = 128; o > 0; o >>= 1) {
        if (c < o) red[c] += red[c + o];
        __syncthreads();
    }
    if (c == 0) g_bf[s*NC + co] = red[0];
}

// ---------------------------------------------------------------------------

extern "C" void kernel_launch(void* const* d_in, const int* in_sizes, int n_in,
                              void* d_out, int out_size)
{
    const float* x        = (const float*)d_in[0];
    const float* y        = (const float*)d_in[1];
    const float* conv_q_w = (const float*)d_in[4];
    const float* bn_q_g   = (const float*)d_in[5];
    const float* bn_q_b   = (const float*)d_in[6];
    const float* conv_k_w = (const float*)d_in[7];
    const float* bn_k_g   = (const float*)d_in[8];
    const float* bn_k_b   = (const float*)d_in[9];
    const float* conv_v_w = (const float*)d_in[10];
    const float* bn_v_g   = (const float*)d_in[11];
    const float* bn_v_b   = (const float*)d_in[12];
    const float* Wq       = (const float*)d_in[13];
    const float* Wk       = (const float*)d_in[14];
    const float* Wv       = (const float*)d_in[15];
    const float* Wo       = (const float*)d_in[16];
    const float* bo       = (const float*)d_in[17];
    float* out = (float*)d_out;

    __half *cv16, *wf16, *ao16, *wo16;
    float *bf;
    cudaGetSymbolAddress((void**)&cv16, g_cv16);
    cudaGetSymbolAddress((void**)&wf16, g_wf16);
    cudaGetSymbolAddress((void**)&ao16, g_ao16);
    cudaGetSymbolAddress((void**)&wo16, g_wo16);
    cudaGetSymbolAddress((void**)&bf, g_bf);

    const int CONV_SMEM  = (CONV_A_H + CONV_B_H) * 2 * 2;         // 74880 B
    const int GEMM_SMEM  = (6144 + 3072) * 2 * 2;                 // 36864 B
    const int ATTN_SMEM  = (2*64*ARS + 2*32*AVS + 64*APS) * 2;    // 32768 B
    cudaFuncSetAttribute(conv_gemm_kernel,
                         cudaFuncAttributeMaxDynamicSharedMemorySize, CONV_SMEM);
    cudaFuncSetAttribute(gemm16_kernel,
                         cudaFuncAttributeMaxDynamicSharedMemorySize, GEMM_SMEM);
    cudaFuncSetAttribute(attn16_kernel,
                         cudaFuncAttributeMaxDynamicSharedMemorySize, ATTN_SMEM);

    // operand conversion + weight layouts
    cvt_xy_kernel<<<dim3(NT*NC/2048, 2), 256>>>(x, y);
    wtrans_kernel<<<dim3(9*NC, 3), 256>>>(conv_q_w, conv_k_w, conv_v_w);
    round_wo_kernel<<<NC*NC/256, 256>>>(Wo);

    // 3 convs, halo implicit GEMM on fp16 tensor cores (ldmatrix fragments)
    conv_gemm_kernel<<<dim3(NT/128, NC/64, 3), 256, CONV_SMEM>>>();

    // BN stats -> fold into fp16 projection weights
    stats_partial_kernel<<<dim3(64, 3), 256>>>();
    stats_final_kernel<<<3, 1024>>>(bn_q_g, bn_q_b, bn_k_g, bn_k_b, bn_v_g, bn_v_b);
    fold_kernel<<<dim3(NC, 3), 256>>>(Wq, Wk, Wv);

    // 3 projections (fp16): Q/K dim-permuted, V transposed token-permuted
    gemm16_kernel<<<dim3(NT/128, NC/64, 3), 256, GEMM_SMEM>>>(
        cv16, cv16 + (long)NT*NC, cv16 + (long)2*NT*NC,
        wf16, (long)NC*NC, bf, nullptr, 1);

    // fp16 flash attention
    attn16_kernel<<<dim3(NB*NH, NL/64), 128, ATTN_SMEM>>>();

    // output projection (fp16 GEMM, fp32 natural output)
    gemm16_kernel<<<dim3(NT/128, NC/64, 1), 256, GEMM_SMEM>>>(
        ao16, ao16, ao16, wo16, 0, bo, out, 0);
}